// round 13
// baseline (speedup 1.0000x reference)
#include <cuda_runtime.h>
#include <math.h>

// Problem constants
#define NIMG   4
#define HW     48
#define CH     3
#define NPIX   6912              // per image
#define KS     21
#define KR     10

// Config: two co-resident blocks per SM (288 = 144*2 <= capacity 296)
#define TPTS   65                // x-grid: t/64, t=0..64
#define GRID   288
#define TB     256
#define YT     2                 // output rows per conv tile (288 = 4n*3c*24)
#define TROWS  (YT + KS - 1)     // 22
#define TCOLS  (HW + KS - 1)     // 68
#define BPI    72                // blocks per image

// Scratch (device globals; no allocation). d_part overwritten each run.
// Transposed layout: [n][t][slice] -> reduce reads 72 contiguous floats.
__device__ __align__(16) float d_part[NIMG][TPTS][BPI];
__device__ unsigned g_cntb[NIMG];
__device__ unsigned g_genb[NIMG];

// Shared pool (floats):
//  persist: IN @0 (1496), KG@1496 KM@1520 KW@1544 (24 ea), M @1568 (96),
//           S @1664 (48), P @1712 (48)
//  P1: H1 @1760 (1056), H2 @2816 (1056)   (ends 3872)
//  P2: PRT @1760 (195, reuses H1)
//  P3: TBL @1760 (66), DF @1832 (1496, ends 3328), H3 @3336 (1056)
#define SP_IN   0
#define SP_KG   1496
#define SP_KM   1520
#define SP_KW   1544
#define SP_M    1568
#define SP_S    1664
#define SP_P    1712
#define SP_H1   1760
#define SP_H2   2816
#define SP_PRT  1760
#define SP_TBL  1760
#define SP_DF   1832
#define SP_H3   3336
#define POOL    4400             // 17600 B static smem (x2 blocks = 35.2 KB/SM)

__device__ __forceinline__ float frcp(float x) {
    float r; asm("rcp.approx.f32 %0, %1;" : "=f"(r) : "f"(x)); return r;
}

// f32x2 packed helpers (FFMA2 via PTX fma.rn.f32x2)
__device__ __forceinline__ unsigned long long pack2(float lo, float hi) {
    unsigned long long d;
    asm("mov.b64 %0, {%1, %2};" : "=l"(d) : "r"(__float_as_uint(lo)), "r"(__float_as_uint(hi)));
    return d;
}
__device__ __forceinline__ void unpack2(unsigned long long v, float& lo, float& hi) {
    unsigned a, b;
    asm("mov.b64 {%0, %1}, %2;" : "=r"(a), "=r"(b) : "l"(v));
    lo = __uint_as_float(a); hi = __uint_as_float(b);
}
__device__ __forceinline__ void fma2(unsigned long long& acc,
                                     unsigned long long a, unsigned long long b) {
    asm("fma.rn.f32x2 %0, %1, %2, %0;" : "+l"(acc) : "l"(a), "l"(b));
}

// Per-image spin barrier, CG-style: fences only in the leader thread.
__device__ __forceinline__ void imgbar(int idx) {
    __syncthreads();
    if (threadIdx.x == 0) {
        volatile unsigned* vgen = (volatile unsigned*)&g_genb[idx];
        __threadfence();                      // order d_part stores before arrive
        unsigned gen = *vgen;
        if (atomicAdd(&g_cntb[idx], 1u) == BPI - 1) {
            g_cntb[idx] = 0;
            __threadfence();
            *vgen = gen + 1;
        } else {
            while (*vgen == gen) {}
        }
        __threadfence();                      // acquire before block reads d_part
    }
    __syncthreads();
}

// One warp builds a unit-L2 1D Gaussian (2D kernel = exact outer product).
__device__ __forceinline__ void make_k1d(float gamma, float* out) {
    int lane = threadIdx.x & 31;
    float inv2s2 = 0.5f * gamma * gamma;
    const float step = (21.0f / 32.0f) / 20.0f;
    const float mean = 21.0f / 64.0f;
    float v = 0.0f;
    if (lane < KS) {
        float d = (float)lane * step - mean;
        v = expf(-d * d * inv2s2);
    }
    float ss = v * v;
    #pragma unroll
    for (int o = 16; o > 0; o >>= 1) ss += __shfl_xor_sync(0xffffffffu, ss, o);
    if (lane < KS) out[lane] = v * rsqrtf(ss);
}

__global__ __launch_bounds__(TB, 2)
void inrf_fused(const float* __restrict__ in,
                const float* __restrict__ gm,
                const float* __restrict__ gw,
                const float* __restrict__ gg,
                float* __restrict__ out) {
    __shared__ float sp[POOL];

    const int tid  = threadIdx.x;
    const int warp = tid >> 5;

    // Decomposition: 288 = 4n * 72; within image: 3c * 24 ytiles (YT=2)
    const int b   = blockIdx.x;
    const int n   = b / BPI;
    const int rem = b % BPI;
    const int c   = rem / 24;
    const int y0  = (rem % 24) * YT;

    // ---------------- Phase 1: convs + per-block partial tanh-table --------
    if      (warp == 0) make_k1d(gg[c], sp + SP_KG);
    else if (warp == 1) make_k1d(gm[c], sp + SP_KM);
    else if (warp == 2) make_k1d(gw[c], sp + SP_KW);

    // zero-padded input tile (rows y0-10..y0+11, cols -10..57), channel c
    for (int i = tid; i < TROWS * TCOLS; i += TB) {
        int r  = i / TCOLS;
        int xc = i % TCOLS - KR;
        int yy = y0 - KR + r;
        float v = 0.0f;
        if ((unsigned)yy < HW && (unsigned)xc < HW)
            v = in[((n * HW + yy) * HW + xc) * CH + c];
        sp[SP_IN + i] = v;
    }
    __syncthreads();

    // packed taps (lo=G, hi=M) -> registers
    unsigned long long tk[KS];
    #pragma unroll
    for (int k = 0; k < KS; k++) tk[k] = pack2(sp[SP_KG + k], sp[SP_KM + k]);

    // horizontal pass, both convs (packed FMA, 3 independent chains)
    for (int i = tid; i < TROWS * HW; i += TB) {
        int r = i / HW, x = i % HW;
        const float* row = sp + SP_IN + r * TCOLS + x;
        unsigned long long a0 = 0ull, a1 = 0ull, a2 = 0ull;
        #pragma unroll
        for (int k = 0; k < 7; k++) {
            float v0 = row[k], v1 = row[k + 7], v2 = row[k + 14];
            fma2(a0, pack2(v0, v0), tk[k]);
            fma2(a1, pack2(v1, v1), tk[k + 7]);
            fma2(a2, pack2(v2, v2), tk[k + 14]);
        }
        float s1a, s2a, s1b, s2b, s1c, s2c;
        unpack2(a0, s1a, s2a); unpack2(a1, s1b, s2b); unpack2(a2, s1c, s2c);
        sp[SP_H1 + i] = (s1a + s1b) + s1c;     // G partial
        sp[SP_H2 + i] = (s2a + s2b) + s2c;     // M partial
    }
    __syncthreads();

    // vertical pass (96 threads, 3 chains): M -> smem; F = e^{-2 blur};
    // pair-fold F via shfl: S = F0+F1, P = F0*F1 per adjacent pixel pair.
    if (tid < YT * HW) {
        int yo = tid / HW, x = tid % HW;
        unsigned long long a0 = 0ull, a1 = 0ull, a2 = 0ull;
        #pragma unroll
        for (int k = 0; k < 7; k++) {
            int o0 = (yo + k) * HW + x;
            int o1 = (yo + k + 7) * HW + x;
            int o2 = (yo + k + 14) * HW + x;
            fma2(a0, pack2(sp[SP_H1 + o0], sp[SP_H2 + o0]), tk[k]);
            fma2(a1, pack2(sp[SP_H1 + o1], sp[SP_H2 + o1]), tk[k + 7]);
            fma2(a2, pack2(sp[SP_H1 + o2], sp[SP_H2 + o2]), tk[k + 14]);
        }
        float g0, m0, g1, m1, g2, m2;
        unpack2(a0, g0, m0); unpack2(a1, g1, m1); unpack2(a2, g2, m2);
        sp[SP_M + tid] = (m0 + m1) + m2;
        float F  = __expf(-2.0f * ((g0 + g1) + g2));
        float Fo = __shfl_xor_sync(0xffffffffu, F, 1);
        if ((tid & 1) == 0) {
            sp[SP_S + (tid >> 1)] = F + Fo;
            sp[SP_P + (tid >> 1)] = F * Fo;
        }
    }
    __syncthreads();

    // partial table (pairwise): prt[t*3+part] = sum over 16 pairs of
    //   (2 + E*S) / (1 + E*S + E^2*P)  == 1/(1+E F0) + 1/(1+E F1)
    // 195 threads, 4 independent rcp chains, 1 MUFU per 2 pixels.
    if (tid < 3 * TPTS) {
        int t    = tid / 3;
        int part = tid - 3 * t;
        float E  = __expf((float)t * (2.0f / 64.0f));
        float E2 = E * E;
        float a0 = 0.f, a1 = 0.f, a2 = 0.f, a3 = 0.f;
        #pragma unroll
        for (int k = 0; k < 16; k += 4) {
            float s0 = sp[SP_S + part + 3 * (k + 0)], p0 = sp[SP_P + part + 3 * (k + 0)];
            float s1 = sp[SP_S + part + 3 * (k + 1)], p1 = sp[SP_P + part + 3 * (k + 1)];
            float s2 = sp[SP_S + part + 3 * (k + 2)], p2 = sp[SP_P + part + 3 * (k + 2)];
            float s3 = sp[SP_S + part + 3 * (k + 3)], p3 = sp[SP_P + part + 3 * (k + 3)];
            a0 += fmaf(E, s0, 2.0f) * frcp(fmaf(E2, p0, fmaf(E, s0, 1.0f)));
            a1 += fmaf(E, s1, 2.0f) * frcp(fmaf(E2, p1, fmaf(E, s1, 1.0f)));
            a2 += fmaf(E, s2, 2.0f) * frcp(fmaf(E2, p2, fmaf(E, s2, 1.0f)));
            a3 += fmaf(E, s3, 2.0f) * frcp(fmaf(E2, p3, fmaf(E, s3, 1.0f)));
        }
        sp[SP_PRT + tid] = (a0 + a1) + (a2 + a3);
    }
    __syncthreads();

    // write this block's 65-entry partial column (transposed, replay-safe)
    if (tid < TPTS) {
        const float* q = sp + SP_PRT + 3 * tid;
        d_part[n][tid][rem] = (q[0] + q[1]) + q[2];
    }

    imgbar(n);                                 // single per-image barrier

    // ---------------- Phase 3: reduce table; out = M - W(diff) -------------
    // merged reduce+table: 65 threads, 18 contiguous float4 loads (MLP 18)
    if (tid < TPTS) {
        const float4* p4 = (const float4*)&d_part[n][tid][0];
        float a0 = 0.f, a1 = 0.f, a2 = 0.f, a3 = 0.f;
        #pragma unroll
        for (int s = 0; s < 18; s += 3) {
            float4 v0 = p4[s], v1 = p4[s + 1], v2 = p4[s + 2];
            a0 += v0.x + v0.y;  a1 += v0.z + v0.w;
            a2 += v1.x + v1.y;  a3 += v1.z + v1.w;
            a0 += v2.x + v2.y;  a1 += v2.z + v2.w;
        }
        float s = (a0 + a1) + (a2 + a3);
        sp[SP_TBL + tid] = 1.0f - s * (2.0f / (float)NPIX);
    }
    float tw[KS];
    #pragma unroll
    for (int k = 0; k < KS; k++) tw[k] = sp[SP_KW + k];
    __syncthreads();

    // diff tile from persisted IN tile (zero outside the image)
    for (int i = tid; i < TROWS * TCOLS; i += TB) {
        int r  = i / TCOLS;
        int xc = i % TCOLS - KR;
        int yy = y0 - KR + r;
        float d = 0.0f;
        if ((unsigned)yy < HW && (unsigned)xc < HW) {
            float u = sp[SP_IN + i] * 64.0f;
            u = fminf(fmaxf(u, 0.0f), 63.999f);
            int   i0 = (int)u;
            float fr = u - (float)i0;
            float t0 = sp[SP_TBL + i0], t1 = sp[SP_TBL + i0 + 1];
            d = fmaf(t1 - t0, fr, t0);
        }
        sp[SP_DF + i] = d;
    }
    __syncthreads();

    // horizontal pass (W conv, 3 independent chains)
    for (int i = tid; i < TROWS * HW; i += TB) {
        int r = i / HW, x = i % HW;
        const float* row = sp + SP_DF + r * TCOLS + x;
        float a0 = 0.f, a1 = 0.f, a2 = 0.f;
        #pragma unroll
        for (int k = 0; k < 7; k++) {
            a0 = fmaf(row[k],      tw[k],      a0);
            a1 = fmaf(row[k + 7],  tw[k + 7],  a1);
            a2 = fmaf(row[k + 14], tw[k + 14], a2);
        }
        sp[SP_H3 + i] = (a0 + a1) + a2;
    }
    __syncthreads();

    // vertical pass (96 threads, 3 chains) + final subtraction (L = 1)
    if (tid < YT * HW) {
        int yo = tid / HW, x = tid % HW;
        float a0 = 0.f, a1 = 0.f, a2 = 0.f;
        #pragma unroll
        for (int k = 0; k < 7; k++) {
            a0 = fmaf(sp[SP_H3 + (yo + k) * HW + x],      tw[k],      a0);
            a1 = fmaf(sp[SP_H3 + (yo + k + 7) * HW + x],  tw[k + 7],  a1);
            a2 = fmaf(sp[SP_H3 + (yo + k + 14) * HW + x], tw[k + 14], a2);
        }
        float sw = (a0 + a1) + a2;
        out[((n * HW + y0 + yo) * HW + x) * CH + c] = sp[SP_M + tid] - sw;
    }
}

extern "C" void kernel_launch(void* const* d_in, const int* in_sizes, int n_in,
                              void* d_out, int out_size) {
    const float* in = (const float*)d_in[0];
    const float* gm = (const float*)d_in[1];
    const float* gw = (const float*)d_in[2];
    const float* gg = (const float*)d_in[3];
    float* out = (float*)d_out;

    inrf_fused<<<GRID, TB>>>(in, gm, gw, gg, out);
}

// round 14
// speedup vs baseline: 1.1373x; 1.1373x over previous
#include <cuda_runtime.h>
#include <math.h>

// Problem constants
#define NIMG   4
#define HW     48
#define CH     3
#define NPIX   6912              // per image
#define KS     21
#define KR     10

// Config
#define TPTS   65                // x-grid: t/64, t=0..64
#define GRID   144               // 1 block/SM -> all co-resident, safe spin barrier
#define TB     512
#define YT     4                 // output rows per conv tile (144 = 4n*3c*12)
#define TROWS  (YT + KS - 1)     // 24
#define TCOLS  (HW + KS - 1)     // 68
#define BPI    36                // blocks per image

// Scratch (device globals; no allocation). d_part overwritten each run.
// Transposed layout: [n][t][slice] -> reduce reads 36 contiguous floats.
__device__ __align__(16) float d_part[NIMG][TPTS][BPI];
__device__ unsigned g_cntb[NIMG];
__device__ unsigned g_genb[NIMG];

// Shared pool (floats):
//  persist: IN @0 (1632), KG@1632 KM@1656 KW@1680, M @1704 (192),
//           S @1896 (96), P @1992 (96)
//  P1: H1 @2088 (1152), H2 @3240 (1152)
//  P2: PRT @2088 (390, reuses H1)
//  P3: TBL @2088 (66), DF @2160 (1632), H3 @3852 (1152)
#define SP_IN   0
#define SP_KG   1632
#define SP_KM   1656
#define SP_KW   1680
#define SP_M    1704
#define SP_S    1896
#define SP_P    1992
#define SP_H1   2088
#define SP_H2   3240
#define SP_PRT  2088
#define SP_TBL  2088
#define SP_DF   2160
#define SP_H3   3852
#define POOL    5056             // 20224 B static smem

__device__ __forceinline__ float frcp(float x) {
    float r; asm("rcp.approx.f32 %0, %1;" : "=f"(r) : "f"(x)); return r;
}

// f32x2 packed helpers (FFMA2 via PTX fma.rn.f32x2)
__device__ __forceinline__ unsigned long long pack2(float lo, float hi) {
    unsigned long long d;
    asm("mov.b64 %0, {%1, %2};" : "=l"(d) : "r"(__float_as_uint(lo)), "r"(__float_as_uint(hi)));
    return d;
}
__device__ __forceinline__ void unpack2(unsigned long long v, float& lo, float& hi) {
    unsigned a, b;
    asm("mov.b64 {%0, %1}, %2;" : "=r"(a), "=r"(b) : "l"(v));
    lo = __uint_as_float(a); hi = __uint_as_float(b);
}
__device__ __forceinline__ void fma2(unsigned long long& acc,
                                     unsigned long long a, unsigned long long b) {
    asm("fma.rn.f32x2 %0, %1, %2, %0;" : "+l"(acc) : "l"(a), "l"(b));
}

// Per-image spin barrier, CG-style: fences only in the leader thread.
__device__ __forceinline__ void imgbar(int idx) {
    __syncthreads();
    if (threadIdx.x == 0) {
        volatile unsigned* vgen = (volatile unsigned*)&g_genb[idx];
        __threadfence();                      // order d_part stores before arrive
        unsigned gen = *vgen;
        if (atomicAdd(&g_cntb[idx], 1u) == BPI - 1) {
            g_cntb[idx] = 0;
            __threadfence();
            *vgen = gen + 1;
        } else {
            while (*vgen == gen) {}
        }
        __threadfence();                      // acquire before block reads d_part
    }
    __syncthreads();
}

// One warp builds a unit-L2 1D Gaussian (2D kernel = exact outer product).
__device__ __forceinline__ void make_k1d(float gamma, float* out) {
    int lane = threadIdx.x & 31;
    float inv2s2 = 0.5f * gamma * gamma;
    const float step = (21.0f / 32.0f) / 20.0f;
    const float mean = 21.0f / 64.0f;
    float v = 0.0f;
    if (lane < KS) {
        float d = (float)lane * step - mean;
        v = expf(-d * d * inv2s2);
    }
    float ss = v * v;
    #pragma unroll
    for (int o = 16; o > 0; o >>= 1) ss += __shfl_xor_sync(0xffffffffu, ss, o);
    if (lane < KS) out[lane] = v * rsqrtf(ss);
}

__global__ __launch_bounds__(TB, 1)
void inrf_fused(const float* __restrict__ in,
                const float* __restrict__ gm,
                const float* __restrict__ gw,
                const float* __restrict__ gg,
                float* __restrict__ out) {
    __shared__ float sp[POOL];

    const int tid  = threadIdx.x;
    const int warp = tid >> 5;

    // Decomposition: 144 = 4n * 36; within image: 3c * 12 ytiles
    const int b   = blockIdx.x;
    const int n   = b / BPI;
    const int rem = b % BPI;
    const int c   = rem / 12;
    const int y0  = (rem % 12) * YT;

    // ---------------- Phase 1: convs + per-block partial tanh-table --------
    if      (warp == 0) make_k1d(gg[c], sp + SP_KG);
    else if (warp == 1) make_k1d(gm[c], sp + SP_KM);
    else if (warp == 2) make_k1d(gw[c], sp + SP_KW);

    // zero-padded input tile (rows y0-10..y0+13, cols -10..57), channel c
    for (int i = tid; i < TROWS * TCOLS; i += TB) {
        int r  = i / TCOLS;
        int xc = i % TCOLS - KR;
        int yy = y0 - KR + r;
        float v = 0.0f;
        if ((unsigned)yy < HW && (unsigned)xc < HW)
            v = in[((n * HW + yy) * HW + xc) * CH + c];
        sp[SP_IN + i] = v;
    }
    __syncthreads();

    // packed taps (lo=G, hi=M) -> registers
    unsigned long long tk[KS];
    #pragma unroll
    for (int k = 0; k < KS; k++) tk[k] = pack2(sp[SP_KG + k], sp[SP_KM + k]);

    // horizontal pass, both convs (packed FMA, 3 independent chains)
    for (int i = tid; i < TROWS * HW; i += TB) {
        int r = i / HW, x = i % HW;
        const float* row = sp + SP_IN + r * TCOLS + x;
        unsigned long long a0 = 0ull, a1 = 0ull, a2 = 0ull;
        #pragma unroll
        for (int k = 0; k < 7; k++) {
            float v0 = row[k], v1 = row[k + 7], v2 = row[k + 14];
            fma2(a0, pack2(v0, v0), tk[k]);
            fma2(a1, pack2(v1, v1), tk[k + 7]);
            fma2(a2, pack2(v2, v2), tk[k + 14]);
        }
        float s1a, s2a, s1b, s2b, s1c, s2c;
        unpack2(a0, s1a, s2a); unpack2(a1, s1b, s2b); unpack2(a2, s1c, s2c);
        sp[SP_H1 + i] = (s1a + s1b) + s1c;     // G partial
        sp[SP_H2 + i] = (s2a + s2b) + s2c;     // M partial
    }
    __syncthreads();

    // vertical pass (192 threads, 3 chains): M -> smem; F = e^{-2 blur};
    // pair-fold F via shfl: S = F0+F1, P = F0*F1 per adjacent pixel pair.
    if (tid < YT * HW) {
        int yo = tid / HW, x = tid % HW;
        unsigned long long a0 = 0ull, a1 = 0ull, a2 = 0ull;
        #pragma unroll
        for (int k = 0; k < 7; k++) {
            int o0 = (yo + k) * HW + x;
            int o1 = (yo + k + 7) * HW + x;
            int o2 = (yo + k + 14) * HW + x;
            fma2(a0, pack2(sp[SP_H1 + o0], sp[SP_H2 + o0]), tk[k]);
            fma2(a1, pack2(sp[SP_H1 + o1], sp[SP_H2 + o1]), tk[k + 7]);
            fma2(a2, pack2(sp[SP_H1 + o2], sp[SP_H2 + o2]), tk[k + 14]);
        }
        float g0, m0, g1, m1, g2, m2;
        unpack2(a0, g0, m0); unpack2(a1, g1, m1); unpack2(a2, g2, m2);
        sp[SP_M + tid] = (m0 + m1) + m2;
        float F  = __expf(-2.0f * ((g0 + g1) + g2));
        float Fo = __shfl_xor_sync(0xffffffffu, F, 1);
        if ((tid & 1) == 0) {
            sp[SP_S + (tid >> 1)] = F + Fo;
            sp[SP_P + (tid >> 1)] = F * Fo;
        }
    }
    __syncthreads();

    // partial table (pairwise): prt[t*6+part] = sum over 16 pairs of
    //   (2 + E*S) / (1 + E*S + E^2*P)   == 1/(1+E F0) + 1/(1+E F1)
    // 390 threads, 4 independent rcp chains, 1 MUFU per 2 pixels.
    if (tid < 6 * TPTS) {
        int t    = tid / 6;
        int part = tid - 6 * t;
        float E  = __expf((float)t * (2.0f / 64.0f));
        float E2 = E * E;
        float a0 = 0.f, a1 = 0.f, a2 = 0.f, a3 = 0.f;
        #pragma unroll
        for (int k = 0; k < 16; k += 4) {
            float s0 = sp[SP_S + part + 6 * (k + 0)], p0 = sp[SP_P + part + 6 * (k + 0)];
            float s1 = sp[SP_S + part + 6 * (k + 1)], p1 = sp[SP_P + part + 6 * (k + 1)];
            float s2 = sp[SP_S + part + 6 * (k + 2)], p2 = sp[SP_P + part + 6 * (k + 2)];
            float s3 = sp[SP_S + part + 6 * (k + 3)], p3 = sp[SP_P + part + 6 * (k + 3)];
            a0 += fmaf(E, s0, 2.0f) * frcp(fmaf(E2, p0, fmaf(E, s0, 1.0f)));
            a1 += fmaf(E, s1, 2.0f) * frcp(fmaf(E2, p1, fmaf(E, s1, 1.0f)));
            a2 += fmaf(E, s2, 2.0f) * frcp(fmaf(E2, p2, fmaf(E, s2, 1.0f)));
            a3 += fmaf(E, s3, 2.0f) * frcp(fmaf(E2, p3, fmaf(E, s3, 1.0f)));
        }
        sp[SP_PRT + tid] = (a0 + a1) + (a2 + a3);
    }
    __syncthreads();

    // write this block's 65-entry partial column (transposed, replay-safe)
    if (tid < TPTS) {
        const float* q = sp + SP_PRT + 6 * tid;
        d_part[n][tid][rem] = ((q[0] + q[1]) + (q[2] + q[3])) + (q[4] + q[5]);
    }

    imgbar(n);                                 // single per-image barrier

    // ---------------- Phase 3: reduce table; out = M - W(diff) -------------
    // merged reduce+table: 65 threads, 9 contiguous float4 loads each (MLP 9)
    if (tid < TPTS) {
        const float4* p4 = (const float4*)&d_part[n][tid][0];
        float a0 = 0.f, a1 = 0.f, a2 = 0.f, a3 = 0.f;
        #pragma unroll
        for (int s = 0; s < 9; s += 3) {
            float4 v0 = p4[s], v1 = p4[s + 1], v2 = p4[s + 2];
            a0 += v0.x + v0.y;  a1 += v0.z + v0.w;
            a2 += v1.x + v1.y;  a3 += v1.z + v1.w;
            a0 += v2.x + v2.y;  a1 += v2.z + v2.w;
        }
        float s = (a0 + a1) + (a2 + a3);
        sp[SP_TBL + tid] = 1.0f - s * (2.0f / (float)NPIX);
    }
    float tw[KS];
    #pragma unroll
    for (int k = 0; k < KS; k++) tw[k] = sp[SP_KW + k];
    __syncthreads();

    // diff tile from persisted IN tile (zero outside the image)
    for (int i = tid; i < TROWS * TCOLS; i += TB) {
        int r  = i / TCOLS;
        int xc = i % TCOLS - KR;
        int yy = y0 - KR + r;
        float d = 0.0f;
        if ((unsigned)yy < HW && (unsigned)xc < HW) {
            float u = sp[SP_IN + i] * 64.0f;
            u = fminf(fmaxf(u, 0.0f), 63.999f);
            int   i0 = (int)u;
            float fr = u - (float)i0;
            float t0 = sp[SP_TBL + i0], t1 = sp[SP_TBL + i0 + 1];
            d = fmaf(t1 - t0, fr, t0);
        }
        sp[SP_DF + i] = d;
    }
    __syncthreads();

    // horizontal pass (W conv, 3 independent chains)
    for (int i = tid; i < TROWS * HW; i += TB) {
        int r = i / HW, x = i % HW;
        const float* row = sp + SP_DF + r * TCOLS + x;
        float a0 = 0.f, a1 = 0.f, a2 = 0.f;
        #pragma unroll
        for (int k = 0; k < 7; k++) {
            a0 = fmaf(row[k],      tw[k],      a0);
            a1 = fmaf(row[k + 7],  tw[k + 7],  a1);
            a2 = fmaf(row[k + 14], tw[k + 14], a2);
        }
        sp[SP_H3 + i] = (a0 + a1) + a2;
    }
    __syncthreads();

    // vertical pass (192 threads, 3 chains) + final subtraction (L = 1)
    if (tid < YT * HW) {
        int yo = tid / HW, x = tid % HW;
        float a0 = 0.f, a1 = 0.f, a2 = 0.f;
        #pragma unroll
        for (int k = 0; k < 7; k++) {
            a0 = fmaf(sp[SP_H3 + (yo + k) * HW + x],      tw[k],      a0);
            a1 = fmaf(sp[SP_H3 + (yo + k + 7) * HW + x],  tw[k + 7],  a1);
            a2 = fmaf(sp[SP_H3 + (yo + k + 14) * HW + x], tw[k + 14], a2);
        }
        float sw = (a0 + a1) + a2;
        out[((n * HW + y0 + yo) * HW + x) * CH + c] = sp[SP_M + tid] - sw;
    }
}

extern "C" void kernel_launch(void* const* d_in, const int* in_sizes, int n_in,
                              void* d_out, int out_size) {
    const float* in = (const float*)d_in[0];
    const float* gm = (const float*)d_in[1];
    const float* gw = (const float*)d_in[2];
    const float* gg = (const float*)d_in[3];
    float* out = (float*)d_out;

    inrf_fused<<<GRID, TB>>>(in, gm, gw, gg, out);
}

// round 15
// speedup vs baseline: 1.3851x; 1.2179x over previous
#include <cuda_runtime.h>
#include <math.h>

// Problem constants
#define NIMG   4
#define HW     48
#define CH     3
#define NPIX   6912              // per image
#define KS     21
#define KR     10

// Config
#define TPTS   65                // x-grid: t/64, t=0..64
#define GRID   144               // 1 block/SM -> all co-resident, safe spin barrier
#define TB     512
#define YT     4                 // output rows per conv tile (144 = 4n*3c*12)
#define TROWS  (YT + KS - 1)     // 24
#define TCOLS  (HW + KS - 1)     // 68
#define BPI    36                // blocks per image

// Scratch (device globals; no allocation). d_part overwritten each run.
__device__ __align__(16) float d_part[NIMG][TPTS][BPI];
__device__ unsigned g_cntb[NIMG];
__device__ unsigned g_genb[NIMG];

// Shared pool (floats):
//  persist: IN @0 (1632), KG@1632 KM@1656 KW@1680, M @1704 (192),
//           SP @1896 (192 = 96 float2 (S,P) pairs)
//  P1: H12 @2088 (2304 = 1152 float2 (G,M) pairs) ends 4392
//  P2: PRT @2088 (390, reuses H12)
//  P3: TBL @2088 (66), DF @2160 (1632) ends 3792, H3 @3792 (1152) ends 4944
#define SP_IN   0
#define SP_KG   1632
#define SP_KM   1656
#define SP_KW   1680
#define SP_M    1704
#define SP_SP   1896
#define SP_H12  2088
#define SP_PRT  2088
#define SP_TBL  2088
#define SP_DF   2160
#define SP_H3   3792
#define POOL    4944             // 19776 B static smem

typedef unsigned long long ull;

__device__ __forceinline__ float frcp(float x) {
    float r; asm("rcp.approx.f32 %0, %1;" : "=f"(r) : "f"(x)); return r;
}
__device__ __forceinline__ ull pack2(float lo, float hi) {
    ull d;
    asm("mov.b64 %0, {%1, %2};" : "=l"(d) : "r"(__float_as_uint(lo)), "r"(__float_as_uint(hi)));
    return d;
}
__device__ __forceinline__ void unpack2(ull v, float& lo, float& hi) {
    unsigned a, b;
    asm("mov.b64 {%0, %1}, %2;" : "=r"(a), "=r"(b) : "l"(v));
    lo = __uint_as_float(a); hi = __uint_as_float(b);
}
__device__ __forceinline__ void fma2(ull& acc, ull a, ull b) {
    asm("fma.rn.f32x2 %0, %1, %2, %0;" : "+l"(acc) : "l"(a), "l"(b));
}
__device__ __forceinline__ void add2(ull& a, ull b) {
    asm("add.rn.f32x2 %0, %0, %1;" : "+l"(a) : "l"(b));
}

// Per-image spin barrier, CG-style: fences only in the leader thread.
__device__ __forceinline__ void imgbar(int idx) {
    __syncthreads();
    if (threadIdx.x == 0) {
        volatile unsigned* vgen = (volatile unsigned*)&g_genb[idx];
        __threadfence();                      // order d_part stores before arrive
        unsigned gen = *vgen;
        if (atomicAdd(&g_cntb[idx], 1u) == BPI - 1) {
            g_cntb[idx] = 0;
            __threadfence();
            *vgen = gen + 1;
        } else {
            while (*vgen == gen) {}
        }
        __threadfence();                      // acquire before block reads d_part
    }
    __syncthreads();
}

// One warp builds a unit-L2 1D Gaussian (2D kernel = exact outer product).
__device__ __forceinline__ void make_k1d(float gamma, float* out) {
    int lane = threadIdx.x & 31;
    float inv2s2 = 0.5f * gamma * gamma;
    const float step = (21.0f / 32.0f) / 20.0f;
    const float mean = 21.0f / 64.0f;
    float v = 0.0f;
    if (lane < KS) {
        float d = (float)lane * step - mean;
        v = expf(-d * d * inv2s2);
    }
    float ss = v * v;
    #pragma unroll
    for (int o = 16; o > 0; o >>= 1) ss += __shfl_xor_sync(0xffffffffu, ss, o);
    if (lane < KS) out[lane] = v * rsqrtf(ss);
}

__global__ __launch_bounds__(TB, 1)
void inrf_fused(const float* __restrict__ in,
                const float* __restrict__ gm,
                const float* __restrict__ gw,
                const float* __restrict__ gg,
                float* __restrict__ out) {
    __shared__ float sp[POOL];

    const int tid  = threadIdx.x;
    const int warp = tid >> 5;

    // Decomposition: 144 = 4n * 36; within image: 3c * 12 ytiles
    const int b   = blockIdx.x;
    const int n   = b / BPI;
    const int rem = b % BPI;
    const int c   = rem / 12;
    const int y0  = (rem % 12) * YT;

    // ---------------- Phase 1: convs + per-block partial tanh-table --------
    if      (warp == 0) make_k1d(gg[c], sp + SP_KG);
    else if (warp == 1) make_k1d(gm[c], sp + SP_KM);
    else if (warp == 2) make_k1d(gw[c], sp + SP_KW);

    // zero-padded input tile (rows y0-10..y0+13, cols -10..57), channel c
    for (int i = tid; i < TROWS * TCOLS; i += TB) {
        int r  = i / TCOLS;
        int xc = i % TCOLS - KR;
        int yy = y0 - KR + r;
        float v = 0.0f;
        if ((unsigned)yy < HW && (unsigned)xc < HW)
            v = in[((n * HW + yy) * HW + xc) * CH + c];
        sp[SP_IN + i] = v;
    }
    __syncthreads();

    // packed taps (lo=G, hi=M) -> registers
    ull tk[KS];
    #pragma unroll
    for (int k = 0; k < KS; k++) tk[k] = pack2(sp[SP_KG + k], sp[SP_KM + k]);

    // horizontal pass, both convs: 3 outputs/thread streaming window.
    // 384 threads: r = tid>>4, x0 = 3*(tid&15); 23 loads -> 3 sliding accs.
    if (tid < 384) {
        const int r  = tid >> 4;
        const int x0 = 3 * (tid & 15);
        const float* row = sp + SP_IN + r * TCOLS + x0;
        ull a0 = 0ull, a1 = 0ull, a2 = 0ull;
        #pragma unroll
        for (int j = 0; j < 23; j++) {
            float v = row[j];
            ull vv = pack2(v, v);
            if (j <= 20)           fma2(a0, vv, tk[j]);
            if (j >= 1 && j <= 21) fma2(a1, vv, tk[j - 1]);
            if (j >= 2)            fma2(a2, vv, tk[j - 2]);
        }
        ull* H12 = (ull*)(sp + SP_H12);
        H12[r * HW + x0]     = a0;    // (G,M) pairs
        H12[r * HW + x0 + 1] = a1;
        H12[r * HW + x0 + 2] = a2;
    }
    __syncthreads();

    // vertical pass (192 threads): 1 LDS.64 + 1 FFMA2 per tap, 3 chains.
    // M -> smem; F = e^{-2 blur}; pair-fold (S,P) to float2 via shfl.
    if (tid < YT * HW) {
        int yo = tid / HW, x = tid % HW;
        const ull* H12 = (const ull*)(sp + SP_H12);
        ull a0 = 0ull, a1 = 0ull, a2 = 0ull;
        #pragma unroll
        for (int k = 0; k < 7; k++) {
            fma2(a0, H12[(yo + k) * HW + x],      tk[k]);
            fma2(a1, H12[(yo + k + 7) * HW + x],  tk[k + 7]);
            fma2(a2, H12[(yo + k + 14) * HW + x], tk[k + 14]);
        }
        add2(a0, a1); add2(a0, a2);
        float g, m; unpack2(a0, g, m);
        sp[SP_M + tid] = m;
        float F  = __expf(-2.0f * g);
        float Fo = __shfl_xor_sync(0xffffffffu, F, 1);
        if ((tid & 1) == 0) {
            ull* SPp = (ull*)(sp + SP_SP);
            SPp[tid >> 1] = pack2(F + Fo, F * Fo);   // (S, P)
        }
    }
    __syncthreads();

    // partial table (pairwise): prt[t*6+part] = sum over 16 pairs of
    //   (2 + E*S)/(1 + E*S + E^2*P)  == 1/(1+E F0) + 1/(1+E F1)
    if (tid < 6 * TPTS) {
        int t    = tid / 6;
        int part = tid - 6 * t;
        float E  = __expf((float)t * (2.0f / 64.0f));
        float E2 = E * E;
        const float2* SPp = (const float2*)(sp + SP_SP);
        float a0 = 0.f, a1 = 0.f, a2 = 0.f, a3 = 0.f;
        #pragma unroll
        for (int k = 0; k < 16; k += 4) {
            float2 v0 = SPp[part + 6 * (k + 0)];
            float2 v1 = SPp[part + 6 * (k + 1)];
            float2 v2 = SPp[part + 6 * (k + 2)];
            float2 v3 = SPp[part + 6 * (k + 3)];
            a0 += fmaf(E, v0.x, 2.0f) * frcp(fmaf(E2, v0.y, fmaf(E, v0.x, 1.0f)));
            a1 += fmaf(E, v1.x, 2.0f) * frcp(fmaf(E2, v1.y, fmaf(E, v1.x, 1.0f)));
            a2 += fmaf(E, v2.x, 2.0f) * frcp(fmaf(E2, v2.y, fmaf(E, v2.x, 1.0f)));
            a3 += fmaf(E, v3.x, 2.0f) * frcp(fmaf(E2, v3.y, fmaf(E, v3.x, 1.0f)));
        }
        sp[SP_PRT + tid] = (a0 + a1) + (a2 + a3);
    }
    __syncthreads();

    // write this block's 65-entry partial column (transposed, replay-safe)
    if (tid < TPTS) {
        const float* q = sp + SP_PRT + 6 * tid;
        d_part[n][tid][rem] = ((q[0] + q[1]) + (q[2] + q[3])) + (q[4] + q[5]);
    }

    imgbar(n);                                 // single per-image barrier

    // ---------------- Phase 3: reduce table; out = M - W(diff) -------------
    // merged reduce+table: 65 threads, 9 contiguous float4 loads each (MLP 9)
    if (tid < TPTS) {
        const float4* p4 = (const float4*)&d_part[n][tid][0];
        float a0 = 0.f, a1 = 0.f, a2 = 0.f, a3 = 0.f;
        #pragma unroll
        for (int s = 0; s < 9; s += 3) {
            float4 v0 = p4[s], v1 = p4[s + 1], v2 = p4[s + 2];
            a0 += v0.x + v0.y;  a1 += v0.z + v0.w;
            a2 += v1.x + v1.y;  a3 += v1.z + v1.w;
            a0 += v2.x + v2.y;  a1 += v2.z + v2.w;
        }
        float s = (a0 + a1) + (a2 + a3);
        sp[SP_TBL + tid] = 1.0f - s * (2.0f / (float)NPIX);
    }
    float tw[KS];
    #pragma unroll
    for (int k = 0; k < KS; k++) tw[k] = sp[SP_KW + k];
    __syncthreads();

    // diff tile from persisted IN tile (zero outside the image)
    for (int i = tid; i < TROWS * TCOLS; i += TB) {
        int r  = i / TCOLS;
        int xc = i % TCOLS - KR;
        int yy = y0 - KR + r;
        float d = 0.0f;
        if ((unsigned)yy < HW && (unsigned)xc < HW) {
            float u = sp[SP_IN + i] * 64.0f;
            u = fminf(fmaxf(u, 0.0f), 63.999f);
            int   i0 = (int)u;
            float fr = u - (float)i0;
            float t0 = sp[SP_TBL + i0], t1 = sp[SP_TBL + i0 + 1];
            d = fmaf(t1 - t0, fr, t0);
        }
        sp[SP_DF + i] = d;
    }
    __syncthreads();

    // horizontal pass (W conv): 3 outputs/thread streaming window
    if (tid < 384) {
        const int r  = tid >> 4;
        const int x0 = 3 * (tid & 15);
        const float* row = sp + SP_DF + r * TCOLS + x0;
        float a0 = 0.f, a1 = 0.f, a2 = 0.f;
        #pragma unroll
        for (int j = 0; j < 23; j++) {
            float v = row[j];
            if (j <= 20)           a0 = fmaf(v, tw[j],     a0);
            if (j >= 1 && j <= 21) a1 = fmaf(v, tw[j - 1], a1);
            if (j >= 2)            a2 = fmaf(v, tw[j - 2], a2);
        }
        sp[SP_H3 + r * HW + x0]     = a0;
        sp[SP_H3 + r * HW + x0 + 1] = a1;
        sp[SP_H3 + r * HW + x0 + 2] = a2;
    }
    __syncthreads();

    // vertical pass (192 threads, 3 chains) + final subtraction (L = 1)
    if (tid < YT * HW) {
        int yo = tid / HW, x = tid % HW;
        float a0 = 0.f, a1 = 0.f, a2 = 0.f;
        #pragma unroll
        for (int k = 0; k < 7; k++) {
            a0 = fmaf(sp[SP_H3 + (yo + k) * HW + x],      tw[k],      a0);
            a1 = fmaf(sp[SP_H3 + (yo + k + 7) * HW + x],  tw[k + 7],  a1);
            a2 = fmaf(sp[SP_H3 + (yo + k + 14) * HW + x], tw[k + 14], a2);
        }
        float sw = (a0 + a1) + a2;
        out[((n * HW + y0 + yo) * HW + x) * CH + c] = sp[SP_M + tid] - sw;
    }
}

extern "C" void kernel_launch(void* const* d_in, const int* in_sizes, int n_in,
                              void* d_out, int out_size) {
    const float* in = (const float*)d_in[0];
    const float* gm = (const float*)d_in[1];
    const float* gw = (const float*)d_in[2];
    const float* gg = (const float*)d_in[3];
    float* out = (float*)d_out;

    inrf_fused<<<GRID, TB>>>(in, gm, gw, gg, out);
}